// round 12
// baseline (speedup 1.0000x reference)
#include <cuda_runtime.h>
#include <cstdint>
#include <math_constants.h>

// Problem constants (match reference)
#define POOLK 7
#define NUM_ROIS 300
#define FH 50
#define FW 50
#define FC 512

#define NPOS       (FH * FW)                  // 2500
#define BINS_PER_ROI (POOLK * POOLK)          // 49
#define ROI_BYTES  (BINS_PER_ROI * FC * 4)    // 100,352 bytes per ROI
#define ROI_V4     (BINS_PER_ROI * (FC / 4))  // 6272 float4 per ROI

// Scratch (no cudaMalloc allowed)
__device__ float g_fmax[NPOS];

// ---------------------------------------------------------------------------
// Kernel A: fmax[h][w] = max_c feature_maps[h][w][c]
// One WARP per position; each lane: 4 independent float4 loads (MLP=4),
// 15 fmax + 5 shuffles, lane 0 stores. No barriers, no smem.
// ---------------------------------------------------------------------------
__global__ void __launch_bounds__(256) channel_max_kernel(const float* __restrict__ fm) {
    const int gtid = blockIdx.x * 256 + threadIdx.x;
    const int pos  = gtid >> 5;
    const int lane = gtid & 31;
    if (pos >= NPOS) return;

    const float4* __restrict__ p =
        reinterpret_cast<const float4*>(fm + (size_t)pos * FC);

    float4 a = p[lane];
    float4 b = p[lane + 32];
    float4 c = p[lane + 64];
    float4 d = p[lane + 96];

    float m0 = fmaxf(fmaxf(a.x, a.y), fmaxf(a.z, a.w));
    float m1 = fmaxf(fmaxf(b.x, b.y), fmaxf(b.z, b.w));
    float m2 = fmaxf(fmaxf(c.x, c.y), fmaxf(c.z, c.w));
    float m3 = fmaxf(fmaxf(d.x, d.y), fmaxf(d.z, d.w));
    float m  = fmaxf(fmaxf(m0, m1), fmaxf(m2, m3));

    #pragma unroll
    for (int o = 16; o > 0; o >>= 1)
        m = fmaxf(m, __shfl_xor_sync(0xffffffffu, m, o));

    if (lane == 0) g_fmax[pos] = m;
}

// ---------------------------------------------------------------------------
// Kernel B: one CTA per ROI. Compute 49 bin maxes, stage the ROI's full
// 100,352-byte output tile in shared memory, then emit it with a SINGLE
// cp.async.bulk shared->global copy (TMA engine does the 30 MB write).
// ---------------------------------------------------------------------------
__global__ void __launch_bounds__(256) roi_tma_kernel(const float* __restrict__ rois,
                                                      float* __restrict__ out) {
    extern __shared__ float4 sbuf[];          // 6272 float4 = 100,352 B
    __shared__ float s_bin[BINS_PER_ROI];

    const int roi = blockIdx.x;
    const int tid = threadIdx.x;

    // --- 1) bin maxes (threads 0..48), unrolled 5x5 predicated window ---
    if (tid < BINS_PER_ROI) {
        const int bi = tid / POOLK;
        const int bj = tid - bi * POOLK;

        const float* r = rois + (size_t)roi * 5;
        const int x1 = (int)(__ldg(r + 1) * 0.0625f);   // exact /16, non-negative
        const int y1 = (int)(__ldg(r + 2) * 0.0625f);
        const int x2 = (int)(__ldg(r + 3) * 0.0625f);
        const int y2 = (int)(__ldg(r + 4) * 0.0625f);
        const int rh = y2 - y1 + 1;                     // <= 26
        const int rw = x2 - x1 + 1;                     // <= 26

        int hs = y1 + (bi * rh) / POOLK;
        int he = y1 + ((bi + 1) * rh + POOLK - 1) / POOLK;
        int ws = x1 + (bj * rw) / POOLK;
        int we = x1 + ((bj + 1) * rw + POOLK - 1) / POOLK;
        hs = min(max(hs, 0), FH);  he = min(max(he, 0), FH);
        ws = min(max(ws, 0), FW);  we = min(max(we, 0), FW);

        const int hh = he - hs;   // <= 5
        const int ww = we - ws;   // <= 5

        float m = -CUDART_INF_F;
        #pragma unroll
        for (int dr = 0; dr < 5; ++dr) {
            #pragma unroll
            for (int dc = 0; dc < 5; ++dc) {
                if (dr < hh && dc < ww)
                    m = fmaxf(m, g_fmax[(hs + dr) * FW + (ws + dc)]);
            }
        }
        s_bin[tid] = m;
    }
    __syncthreads();

    // --- 2) stage the broadcast tile in shared memory ---
    for (int i = tid; i < ROI_V4; i += 256) {
        const float f = s_bin[i >> 7];        // 128 float4 per bin
        sbuf[i] = make_float4(f, f, f, f);
    }

    // Order generic-proxy smem writes before the async-proxy TMA read.
    asm volatile("fence.proxy.async.shared::cta;" ::: "memory");
    __syncthreads();

    // --- 3) single bulk store: 100,352 B smem -> gmem ---
    if (tid == 0) {
        uint32_t saddr;
        asm("{ .reg .u64 t; cvta.to.shared.u64 t, %1; cvt.u32.u64 %0, t; }"
            : "=r"(saddr) : "l"(sbuf));
        const char* gptr = (const char*)out + (size_t)roi * ROI_BYTES;
        asm volatile(
            "cp.async.bulk.global.shared::cta.bulk_group [%0], [%1], %2;"
            :: "l"(gptr), "r"(saddr), "r"((uint32_t)ROI_BYTES) : "memory");
        asm volatile("cp.async.bulk.commit_group;" ::: "memory");
        asm volatile("cp.async.bulk.wait_group 0;" ::: "memory");
    }
}

// ---------------------------------------------------------------------------
extern "C" void kernel_launch(void* const* d_in, const int* in_sizes, int n_in,
                              void* d_out, int out_size) {
    const float* rois = (const float*)d_in[0];
    const float* fm   = (const float*)d_in[1];
    if (n_in >= 2 && in_sizes[0] != NUM_ROIS * 5 && in_sizes[1] == NUM_ROIS * 5) {
        rois = (const float*)d_in[1];
        fm   = (const float*)d_in[0];
    }
    float* out = (float*)d_out;

    // Opt in to >48 KB dynamic shared memory (idempotent; host-side, not a
    // stream op, safe under graph capture).
    static int smem_ok = 0;
    if (!smem_ok) {
        cudaFuncSetAttribute(roi_tma_kernel,
                             cudaFuncAttributeMaxDynamicSharedMemorySize,
                             ROI_BYTES + 1024);
        smem_ok = 1;
    }

    channel_max_kernel<<<(NPOS * 32 + 255) / 256, 256>>>(fm);
    roi_tma_kernel<<<NUM_ROIS, 256, ROI_BYTES>>>(rois, out);
}